// round 16
// baseline (speedup 1.0000x reference)
#include <cuda_runtime.h>
#include <cuda_fp16.h>
#include <math.h>
#include <stdint.h>

#define NT 4096      // total tokens (B*L)
#define DM 1024      // d_model
#define DH 4096      // d_hidden
#define NH 16
#define HD 64
#define LSEQ 2048
#define NBATCH 2
#define QSTR 3072    // packed qkv row stride
#define DH2 (2 * DH) // combined gate|hid interleaved width
#define SCQ 0.18033688f   // 0.125 * log2(e)

// ---------------- scratch (static device globals; no runtime alloc) ----------------
__device__ __half g_xnh [NT * DM];
__device__ __half g_qkvh[(size_t)NT * QSTR];
__device__ __half g_atth[NT * DM];
__device__ float  g_x1  [NT * DM];
__device__ __half g_xn2h[NT * DM];
__device__ __half g_hidh [(size_t)NT * DH];
// fp16 weights, NATURAL [K][N] layout (no transpose)
__device__ __half g_wqkv[(size_t)DM * QSTR];
__device__ __half g_wo  [DM * DM];
__device__ __half g_wgh [(size_t)DM * DH2];   // 8-col-block interleaved gate|hid
__device__ __half g_wout[(size_t)DH * DM];

// ---------------- PTX helpers ----------------
__device__ __forceinline__ void cpa16(uint32_t saddr, const void* src) {
    asm volatile("cp.async.cg.shared.global [%0], [%1], 16;\n" :: "r"(saddr), "l"(src));
}
__device__ __forceinline__ uint32_t s2u(const void* p) {
    uint32_t a;
    asm("{ .reg .u64 t; cvta.to.shared.u64 t, %1; cvt.u32.u64 %0, t; }" : "=r"(a) : "l"(p));
    return a;
}
__device__ __forceinline__ void mma_f16(float* c, const unsigned* a, const unsigned* b) {
    asm volatile("mma.sync.aligned.m16n8k16.row.col.f32.f16.f16.f32 "
        "{%0,%1,%2,%3}, {%4,%5,%6,%7}, {%8,%9}, {%0,%1,%2,%3};\n"
        : "+f"(c[0]), "+f"(c[1]), "+f"(c[2]), "+f"(c[3])
        : "r"(a[0]), "r"(a[1]), "r"(a[2]), "r"(a[3]), "r"(b[0]), "r"(b[1]));
}
__device__ __forceinline__ void ldmx4(unsigned* r, uint32_t addr) {
    asm volatile("ldmatrix.sync.aligned.m8n8.x4.shared.b16 {%0,%1,%2,%3}, [%4];"
        : "=r"(r[0]), "=r"(r[1]), "=r"(r[2]), "=r"(r[3]) : "r"(addr));
}
__device__ __forceinline__ void ldmx4t(unsigned* r, uint32_t addr) {
    asm volatile("ldmatrix.sync.aligned.m8n8.x4.trans.shared.b16 {%0,%1,%2,%3}, [%4];"
        : "=r"(r[0]), "=r"(r[1]), "=r"(r[2]), "=r"(r[3]) : "r"(addr));
}
__device__ __forceinline__ float ex2f(float x) {
    float r; asm("ex2.approx.ftz.f32 %0, %1;" : "=f"(r) : "f"(x)); return r;
}

// ---------------- fused fp32->fp16 weight convert (ALL weights, one launch) ----------------
__global__ __launch_bounds__(256) void cvt_all_kernel(
    const float* __restrict__ Wq, const float* __restrict__ Wk, const float* __restrict__ Wv,
    const float* __restrict__ Wo, const float* __restrict__ Wg, const float* __restrict__ Wh,
    const float* __restrict__ Wout2,
    __half* __restrict__ wqkv, __half* __restrict__ wo, __half* __restrict__ wgh,
    __half* __restrict__ wout)
{
    int bx = blockIdx.x;
    const float* in; __half* out; int C, outStride, blk, interleave = 0;
    if (bx < 512)        { in = Wq;   out = wqkv;          C = DM; outStride = QSTR; blk = bx; }
    else if (bx < 1024)  { in = Wk;   out = wqkv + DM;     C = DM; outStride = QSTR; blk = bx - 512; }
    else if (bx < 1536)  { in = Wv;   out = wqkv + 2 * DM; C = DM; outStride = QSTR; blk = bx - 1024; }
    else if (bx < 2048)  { in = Wo;   out = wo;            C = DM; outStride = DM;   blk = bx - 1536; }
    else if (bx < 4096)  { in = Wg;   out = wgh;           C = DH; outStride = DH2;  blk = bx - 2048; interleave = 1; }
    else if (bx < 6144)  { in = Wh;   out = wgh + 8;       C = DH; outStride = DH2;  blk = bx - 4096; interleave = 1; }
    else                 { in = Wout2; out = wout;         C = DM; outStride = DM;   blk = bx - 6144; }

    int idx = blk * 256 + threadIdx.x;
    int tpr = C >> 3;
    int row = idx / tpr;
    int col = (idx - row * tpr) * 8;
    const float4* p = (const float4*)(in + (size_t)row * C + col);
    float4 a = p[0], b = p[1];
    __half2 h0 = __floats2half2_rn(a.x, a.y);
    __half2 h1 = __floats2half2_rn(a.z, a.w);
    __half2 h2 = __floats2half2_rn(b.x, b.y);
    __half2 h3 = __floats2half2_rn(b.z, b.w);
    uint4 v;
    v.x = *(unsigned*)&h0; v.y = *(unsigned*)&h1;
    v.z = *(unsigned*)&h2; v.w = *(unsigned*)&h3;
    int ocol = interleave ? 2 * col : col;
    *(uint4*)(out + (size_t)row * outStride + ocol) = v;
}

// ---------------- RMSNorm: fp32 in -> fp16 out, 2 rows per block ----------------
__global__ __launch_bounds__(256) void rmsnorm_h_kernel(
    const float* __restrict__ x, const float* __restrict__ w, __half* __restrict__ out)
{
    int half = threadIdx.x >> 7;
    int t = threadIdx.x & 127;
    int row = blockIdx.x * 2 + half;
    const float4* xr = (const float4*)(x + (size_t)row * DM);
    float4 v0 = xr[t], v1 = xr[t + 128];
    float s = v0.x * v0.x + v0.y * v0.y + v0.z * v0.z + v0.w * v0.w
            + v1.x * v1.x + v1.y * v1.y + v1.z * v1.z + v1.w * v1.w;
    __shared__ float red[2][4];
    #pragma unroll
    for (int o = 16; o > 0; o >>= 1) s += __shfl_xor_sync(0xffffffffu, s, o);
    if ((t & 31) == 0) red[half][t >> 5] = s;
    __syncthreads();
    float tot = red[half][0] + red[half][1] + red[half][2] + red[half][3];
    float inv = rsqrtf(tot * (1.0f / DM) + 1e-6f);
    const float4* wp = (const float4*)w;
    float4 w0 = wp[t], w1 = wp[t + 128];
    __half2* orow = (__half2*)(out + (size_t)row * DM);
    orow[2 * t]       = __floats2half2_rn(w0.x * v0.x * inv, w0.y * v0.y * inv);
    orow[2 * t + 1]   = __floats2half2_rn(w0.z * v0.z * inv, w0.w * v0.w * inv);
    orow[2 * (t + 128)]     = __floats2half2_rn(w1.x * v1.x * inv, w1.y * v1.y * inv);
    orow[2 * (t + 128) + 1] = __floats2half2_rn(w1.z * v1.z * inv, w1.w * v1.w * inv);
}

// ================= fp16 GEMM, 128x128 tile (proven round-13) — small-N GEMMs =========
#define HBM 128
#define HBN 128
#define HBK 64
#define ASTRH 72
#define BSTRH 136
#define ATILE_B (HBM * ASTRH * 2)
#define BTILE_B (HBK * BSTRH * 2)
#define HSTAGE (ATILE_B + BTILE_B)
#define NSTAGE 3
#define HSMEM  (NSTAGE * HSTAGE)

__device__ __forceinline__ void hload(uint32_t s0, const __half* A, const __half* B,
    int bm, int bn, int K, int N, int kk, int tid)
{
    const __half* Ag = A + (size_t)bm * K + kk;
    const __half* Bg = B + (size_t)kk * N + bn;
    #pragma unroll
    for (int j = 0; j < 4; j++) {
        int idx = tid + 256 * j;
        int ar = idx >> 3, ac = idx & 7;
        cpa16(s0 + (uint32_t)(ar * ASTRH + ac * 8) * 2, Ag + (size_t)ar * K + ac * 8);
        int br = idx >> 4, bc = idx & 15;
        cpa16(s0 + (uint32_t)ATILE_B + (uint32_t)(br * BSTRH + bc * 8) * 2,
              Bg + (size_t)br * N + bc * 8);
    }
    asm volatile("cp.async.commit_group;\n" ::: "memory");
}

template <int OUT_HALF, int HAS_BIAS, int HAS_RES>
__global__ __launch_bounds__(256, 2) void gemm_f16(
    const __half* __restrict__ A, const __half* __restrict__ B, void* __restrict__ Cv,
    int M, int N, int K, const float* __restrict__ bias, const float* __restrict__ res)
{
    extern __shared__ char hsm[];
    uint32_t sbase = s2u(hsm);
    int tid = threadIdx.x;
    int lane = tid & 31, g = lane >> 2, tg = lane & 3;
    int wid = tid >> 5;
    int m_base = (wid >> 1) * 32;
    int n_base = (wid & 1) * 64;
    int bm = blockIdx.y * HBM, bn = blockIdx.x * HBN;
    int lr = lane & 15, lc = lane >> 4;

    float c[2][8][4];
    #pragma unroll
    for (int mt = 0; mt < 2; mt++)
        #pragma unroll
        for (int nt = 0; nt < 8; nt++)
            #pragma unroll
            for (int i = 0; i < 4; i++) c[mt][nt][i] = 0.f;

    const int iters = K / HBK;
    hload(sbase, A, B, bm, bn, K, N, 0, tid);
    hload(sbase + HSTAGE, A, B, bm, bn, K, N, HBK, tid);

    int stage = 0;
    for (int it = 0; it < iters; ++it) {
        if (it + 2 < iters) {
            int ls = stage + 2; if (ls >= NSTAGE) ls -= NSTAGE;
            hload(sbase + (uint32_t)ls * HSTAGE, A, B, bm, bn, K, N, (it + 2) * HBK, tid);
        } else {
            asm volatile("cp.async.commit_group;\n" ::: "memory");
        }
        asm volatile("cp.async.wait_group 2;\n" ::: "memory");
        __syncthreads();

        uint32_t As = sbase + (uint32_t)stage * HSTAGE;
        uint32_t Bs = As + ATILE_B;

        #pragma unroll
        for (int ks = 0; ks < 4; ++ks) {
            unsigned af[2][4];
            #pragma unroll
            for (int mt = 0; mt < 2; ++mt)
                ldmx4(af[mt], As + (uint32_t)((m_base + mt * 16 + lr) * ASTRH
                                              + ks * 16 + lc * 8) * 2);
            #pragma unroll
            for (int ntp = 0; ntp < 4; ++ntp) {
                unsigned bb[4];
                ldmx4t(bb, Bs + (uint32_t)((ks * 16 + lr) * BSTRH
                                           + n_base + ntp * 16 + lc * 8) * 2);
                #pragma unroll
                for (int mt = 0; mt < 2; ++mt) {
                    mma_f16(c[mt][2 * ntp],     af[mt], bb);
                    mma_f16(c[mt][2 * ntp + 1], af[mt], bb + 2);
                }
            }
        }
        __syncthreads();
        if (++stage >= NSTAGE) stage = 0;
    }

    #pragma unroll
    for (int mt = 0; mt < 2; ++mt) {
        #pragma unroll
        for (int nt = 0; nt < 8; ++nt) {
            int row = bm + m_base + mt * 16 + g;
            int col = bn + n_base + nt * 8 + 2 * tg;
            size_t o0 = (size_t)row * N + col;
            size_t o1 = (size_t)(row + 8) * N + col;
            float v00 = c[mt][nt][0], v01 = c[mt][nt][1];
            float v10 = c[mt][nt][2], v11 = c[mt][nt][3];
            if (HAS_BIAS) {
                float b0v = bias[col], b1v = bias[col + 1];
                v00 += b0v; v01 += b1v; v10 += b0v; v11 += b1v;
            }
            if (HAS_RES) {
                float2 r0 = *(const float2*)(res + o0);
                float2 r1 = *(const float2*)(res + o1);
                v00 += r0.x; v01 += r0.y; v10 += r1.x; v11 += r1.y;
            }
            if (OUT_HALF) {
                __half* Ch = (__half*)Cv;
                *(__half2*)(Ch + o0) = __floats2half2_rn(v00, v01);
                *(__half2*)(Ch + o1) = __floats2half2_rn(v10, v11);
            } else {
                float* Cf = (float*)Cv;
                *(float2*)(Cf + o0) = make_float2(v00, v01);
                *(float2*)(Cf + o1) = make_float2(v10, v11);
            }
        }
    }
}

// ================= fp16 GEMM, 128x256 tile, warp 64x64, occ 1 — big-N GEMMs ==========
#define G2BN 256
#define B2STRH 264                             // 256 + 8 pad (33x16B, odd)
#define B2TILE_B (HBK * B2STRH * 2)            // 33792
#define STAGE2 (ATILE_B + B2TILE_B)            // 52224
#define HSMEM2 (NSTAGE * STAGE2)               // 156672

__device__ __forceinline__ void hload2(uint32_t s0, const __half* A, const __half* B,
    int bm, int bn, int K, int N, int kk, int tid)
{
    const __half* Ag = A + (size_t)bm * K + kk;
    const __half* Bg = B + (size_t)kk * N + bn;
    #pragma unroll
    for (int j = 0; j < 4; j++) {
        int idx = tid + 256 * j;
        int ar = idx >> 3, ac = idx & 7;
        cpa16(s0 + (uint32_t)(ar * ASTRH + ac * 8) * 2, Ag + (size_t)ar * K + ac * 8);
    }
    #pragma unroll
    for (int j = 0; j < 8; j++) {
        int idx = tid + 256 * j;                // 0..2047
        int br = idx >> 5, bc = idx & 31;       // B: 64 rows x 32 chunks
        cpa16(s0 + (uint32_t)ATILE_B + (uint32_t)(br * B2STRH + bc * 8) * 2,
              Bg + (size_t)br * N + bc * 8);
    }
    asm volatile("cp.async.commit_group;\n" ::: "memory");
}

template <int QSCALE, int SWIPAIR>
__global__ __launch_bounds__(256, 1) void gemm256_f16(
    const __half* __restrict__ A, const __half* __restrict__ B, __half* __restrict__ C,
    int M, int N, int K)
{
    extern __shared__ char hsm[];
    uint32_t sbase = s2u(hsm);
    int tid = threadIdx.x;
    int lane = tid & 31, g = lane >> 2, tg = lane & 3;
    int wid = tid >> 5;
    int m_base = (wid >> 2) * 64;              // 2 m-warps
    int n_base = (wid & 3) * 64;               // 4 n-warps
    int bm = blockIdx.y * HBM, bn = blockIdx.x * G2BN;
    int lr = lane & 15, lc = lane >> 4;

    float c[4][8][4];
    #pragma unroll
    for (int mt = 0; mt < 4; mt++)
        #pragma unroll
        for (int nt = 0; nt < 8; nt++)
            #pragma unroll
            for (int i = 0; i < 4; i++) c[mt][nt][i] = 0.f;

    const int iters = K / HBK;
    hload2(sbase, A, B, bm, bn, K, N, 0, tid);
    hload2(sbase + STAGE2, A, B, bm, bn, K, N, HBK, tid);

    int stage = 0;
    for (int it = 0; it < iters; ++it) {
        if (it + 2 < iters) {
            int ls = stage + 2; if (ls >= NSTAGE) ls -= NSTAGE;
            hload2(sbase + (uint32_t)ls * STAGE2, A, B, bm, bn, K, N, (it + 2) * HBK, tid);
        } else {
            asm volatile("cp.async.commit_group;\n" ::: "memory");
        }
        asm volatile("cp.async.wait_group 2;\n" ::: "memory");
        __syncthreads();

        uint32_t As = sbase + (uint32_t)stage * STAGE2;
        uint32_t Bs = As + ATILE_B;

        #pragma unroll
        for (int ks = 0; ks < 4; ++ks) {
            unsigned af[4][4];
            #pragma unroll
            for (int mt = 0; mt < 4; ++mt)
                ldmx4(af[mt], As + (uint32_t)((m_base + mt * 16 + lr) * ASTRH
                                              + ks * 16 + lc * 8) * 2);
            #pragma unroll
            for (int ntp = 0; ntp < 4; ++ntp) {
                unsigned bb[4];
                ldmx4t(bb, Bs + (uint32_t)((ks * 16 + lr) * B2STRH
                                           + n_base + ntp * 16 + lc * 8) * 2);
                #pragma unroll
                for (int mt = 0; mt < 4; ++mt) {
                    mma_f16(c[mt][2 * ntp],     af[mt], bb);
                    mma_f16(c[mt][2 * ntp + 1], af[mt], bb + 2);
                }
            }
        }
        __syncthreads();
        if (++stage >= NSTAGE) stage = 0;
    }

    if (SWIPAIR) {
        int NO = N >> 1;
        #pragma unroll
        for (int mt = 0; mt < 4; ++mt) {
            #pragma unroll
            for (int p = 0; p < 4; ++p) {
                int row = bm + m_base + mt * 16 + g;
                int col = ((bn + n_base + p * 16) >> 4) * 8 + 2 * tg;
                size_t o0 = (size_t)row * NO + col;
                size_t o1 = (size_t)(row + 8) * NO + col;
                float g00 = c[mt][2 * p][0], g01 = c[mt][2 * p][1];
                float g10 = c[mt][2 * p][2], g11 = c[mt][2 * p][3];
                float h00 = c[mt][2 * p + 1][0], h01 = c[mt][2 * p + 1][1];
                float h10 = c[mt][2 * p + 1][2], h11 = c[mt][2 * p + 1][3];
                float v00 = h00 * g00 / (1.f + __expf(-g00));
                float v01 = h01 * g01 / (1.f + __expf(-g01));
                float v10 = h10 * g10 / (1.f + __expf(-g10));
                float v11 = h11 * g11 / (1.f + __expf(-g11));
                *(__half2*)(C + o0) = __floats2half2_rn(v00, v01);
                *(__half2*)(C + o1) = __floats2half2_rn(v10, v11);
            }
        }
        return;
    }

    #pragma unroll
    for (int mt = 0; mt < 4; ++mt) {
        #pragma unroll
        for (int nt = 0; nt < 8; ++nt) {
            int row = bm + m_base + mt * 16 + g;
            int col = bn + n_base + nt * 8 + 2 * tg;
            size_t o0 = (size_t)row * N + col;
            size_t o1 = (size_t)(row + 8) * N + col;
            float v00 = c[mt][nt][0], v01 = c[mt][nt][1];
            float v10 = c[mt][nt][2], v11 = c[mt][nt][3];
            if (QSCALE) {
                if (col < DM) { v00 *= SCQ; v01 *= SCQ; v10 *= SCQ; v11 *= SCQ; }
            }
            *(__half2*)(C + o0) = __floats2half2_rn(v00, v01);
            *(__half2*)(C + o1) = __floats2half2_rn(v10, v11);
        }
    }
}

// ================= fp16 flash attention (round-15 proven, Q pre-scaled) ==============
#define FBQ 128
#define FBKV 64
#define FSTRH 72
#define FKV_BYTES (FBKV * FSTRH * 2)
#define FA_SMEM (4 * FKV_BYTES)

__global__ __launch_bounds__(256, 2) void flash_h_kernel(
    const __half* __restrict__ QKV, __half* __restrict__ O)
{
    extern __shared__ __half hsm2[];
    __half* sK = hsm2;
    __half* sV = sK + 2 * FBKV * FSTRH;

    int tid = threadIdx.x;
    int lane = tid & 31, g = lane >> 2, tg = lane & 3;
    int wid = tid >> 5;
    int mrow = wid * 16;

    int bh = blockIdx.y;
    int b = bh >> 4, h = bh & 15;
    int q0 = blockIdx.x * FBQ;
    size_t base = ((size_t)b * LSEQ) * QSTR + (size_t)h * HD;
    const __half* Qp = QKV;
    const __half* Kp = QKV + DM;
    const __half* Vp = QKV + 2 * DM;

    uint32_t sKu = s2u(sK), sVu = s2u(sV);
    int lr = lane & 15, lc = lane >> 4;

    #pragma unroll
    for (int i = 0; i < 4; i++) {
        int flat = tid + 256 * i;
        int r = flat >> 3, c = flat & 7;
        *(uint4*)&sK[r * FSTRH + c * 8] =
            *(const uint4*)(Qp + base + (size_t)(q0 + r) * QSTR + c * 8);
    }
    __syncthreads();
    unsigned aq[4][4];
    #pragma unroll
    for (int ks = 0; ks < 4; ks++)
        ldmx4(aq[ks], sKu + (uint32_t)((mrow + lr) * FSTRH + ks * 16 + lc * 8) * 2);
    __syncthreads();

    #pragma unroll
    for (int j = 0; j < 2; j++) {
        int cid = tid + 256 * j;
        int r = cid >> 3, c = cid & 7;
        cpa16(sKu + (uint32_t)(r * FSTRH + c * 8) * 2,
              Kp + base + (size_t)r * QSTR + c * 8);
        cpa16(sVu + (uint32_t)(r * FSTRH + c * 8) * 2,
              Vp + base + (size_t)r * QSTR + c * 8);
    }
    asm volatile("cp.async.commit_group;\n" ::: "memory");

    float m0 = -1e30f, m1 = -1e30f, l0 = 0.f, l1 = 0.f;
    float co[8][4];
    #pragma unroll
    for (int nt = 0; nt < 8; nt++)
        #pragma unroll
        for (int i = 0; i < 4; i++) co[nt][i] = 0.f;

    int kt = lane >> 3;
    int krow = lane & 7;
    int kn_off = ((kt >> 1) & 1) * 8 + krow;
    int kk_off = (kt & 1) * 8;
    int vrow = lane & 15;
    int vcol = (lane >> 4) << 3;

    const int ITERS = LSEQ / FBKV;
    for (int it = 0; it < ITERS; ++it) {
        if (it + 1 < ITERS) {
            uint32_t stoff = (uint32_t)((it + 1) & 1) * FKV_BYTES;
            size_t kvoff = (size_t)(it + 1) * FBKV * QSTR;
            #pragma unroll
            for (int j = 0; j < 2; j++) {
                int cid = tid + 256 * j;
                int r = cid >> 3, c = cid & 7;
                cpa16(sKu + stoff + (uint32_t)(r * FSTRH + c * 8) * 2,
                      Kp + base + kvoff + (size_t)r * QSTR + c * 8);
                cpa16(sVu + stoff + (uint32_t)(r * FSTRH + c * 8) * 2,
                      Vp + base + kvoff + (size_t)r * QSTR + c * 8);
            }
            asm volatile("cp.async.commit_group;\n" ::: "memory");
            asm volatile("cp.async.wait_group 1;\n" ::: "memory");
        } else {
            asm volatile("cp.async.wait_group 0;\n" ::: "memory");
        }
        __syncthreads();

        int st = it & 1;
        uint32_t kstage = sKu + (uint32_t)st * FKV_BYTES;
        uint32_t vstage = sVu + (uint32_t)st * FKV_BYTES;

        float cs[8][4];
        #pragma unroll
        for (int nt = 0; nt < 8; nt++)
            #pragma unroll
            for (int i = 0; i < 4; i++) cs[nt][i] = 0.f;

        #pragma unroll
        for (int ks = 0; ks < 4; ks++) {
            #pragma unroll
            for (int ntp = 0; ntp < 4; ntp++) {
                unsigned bb[4];
                ldmx4(bb, kstage + (uint32_t)((ntp * 16 + kn_off) * FSTRH
                                              + ks * 16 + kk_off) * 2);
                mma_f16(cs[2 * ntp],     aq[ks], bb);
                mma_f16(cs[2 * ntp + 1], aq[ks], bb + 2);
            }
        }

        float rm0 = -1e30f, rm1 = -1e30f;
        #pragma unroll
        for (int nt = 0; nt < 8; nt++) {
            rm0 = fmaxf(rm0, fmaxf(cs[nt][0], cs[nt][1]));
            rm1 = fmaxf(rm1, fmaxf(cs[nt][2], cs[nt][3]));
        }
        rm0 = fmaxf(rm0, __shfl_xor_sync(0xffffffffu, rm0, 1));
        rm0 = fmaxf(rm0, __shfl_xor_sync(0xffffffffu, rm0, 2));
        rm1 = fmaxf(rm1, __shfl_xor_sync(0xffffffffu, rm1, 1));
        rm1 = fmaxf(rm1, __shfl_xor_sync(0xffffffffu, rm1, 2));
        float mn0 = fmaxf(m0, rm0);
        float mn1 = fmaxf(m1, rm1);

        float ps0 = 0.f, ps1 = 0.f;
        #pragma unroll
        for (int nt = 0; nt < 8; nt++) {
            cs[nt][0] = ex2f(cs[nt][0] - mn0);
            cs[nt][1] = ex2f(cs[nt][1] - mn0);
            cs[nt][2] = ex2f(cs[nt][2] - mn1);
            cs[nt][3] = ex2f(cs[nt][3] - mn1);
            ps0 += cs[nt][0] + cs[nt][1];
            ps1 += cs[nt][2] + cs[nt][3];
        }
        ps0 += __shfl_xor_sync(0xffffffffu, ps0, 1);
        ps0 += __shfl_xor_sync(0xffffffffu, ps0, 2);
        ps1 += __shfl_xor_sync(0xffffffffu, ps1, 1);
        ps1 += __shfl_xor_sync(0xffffffffu, ps1, 2);

        float f0 = ex2f(m0 - mn0);
        float f1 = ex2f(m1 - mn1);
        l0 = l0 * f0 + ps0;
        l1 = l1 * f1 + ps1;
        m0 = mn0; m1 = mn1;
        #pragma unroll
        for (int nt = 0; nt < 8; nt++) {
            co[nt][0] *= f0; co[nt][1] *= f0;
            co[nt][2] *= f1; co[nt][3] *= f1;
        }

        #pragma unroll
        for (int ks = 0; ks < 4; ks++) {
            unsigned ap[4];
            { __half2 hh = __floats2half2_rn(cs[2 * ks][0], cs[2 * ks][1]); ap[0] = *(unsigned*)&hh; }
            { __half2 hh = __floats2half2_rn(cs[2 * ks][2], cs[2 * ks][3]); ap[1] = *(unsigned*)&hh; }
            { __half2 hh = __floats2half2_rn(cs[2 * ks + 1][0], cs[2 * ks + 1][1]); ap[2] = *(unsigned*)&hh; }
            { __half2 hh = __floats2half2_rn(cs[2 * ks + 1][2], cs[2 * ks + 1][3]); ap[3] = *(unsigned*)&hh; }
            #pragma unroll
            for (int ntp = 0; ntp < 4; ntp++) {
                unsigned bb[4];
                ldmx4t(bb, vstage + (uint32_t)((ks * 16 + vrow) * FSTRH
                                               + ntp * 16 + vcol) * 2);
                mma_f16(co[2 * ntp],     ap, bb);
                mma_f16(co[2 * ntp + 1], ap, bb + 2);
            }
        }
        __syncthreads();
    }

    float i0 = 1.f / l0, i1 = 1.f / l1;
    size_t obase = ((size_t)b * LSEQ) * DM + (size_t)h * HD;
    #pragma unroll
    for (int nt = 0; nt < 8; nt++) {
        int col = nt * 8 + 2 * tg;
        size_t o0 = obase + (size_t)(q0 + mrow + g) * DM + col;
        size_t o1 = obase + (size_t)(q0 + mrow + g + 8) * DM + col;
        *(__half2*)(O + o0) = __floats2half2_rn(co[nt][0] * i0, co[nt][1] * i0);
        *(__half2*)(O + o1) = __floats2half2_rn(co[nt][2] * i1, co[nt][3] * i1);
    }
}

// ---------------- launch ----------------
extern "C" void kernel_launch(void* const* d_in, const int* in_sizes, int n_in,
                              void* d_out, int out_size)
{
    const float* x           = (const float*)d_in[0];
    const float* W_q         = (const float*)d_in[1];
    const float* W_k         = (const float*)d_in[2];
    const float* W_v         = (const float*)d_in[3];
    const float* W_o         = (const float*)d_in[4];
    const float* b_o         = (const float*)d_in[5];
    const float* attn_norm_w = (const float*)d_in[6];
    const float* ffn_norm_w  = (const float*)d_in[7];
    const float* W_gate      = (const float*)d_in[8];
    const float* W_hidden    = (const float*)d_in[9];
    const float* W_out       = (const float*)d_in[10];
    const float* b_out       = (const float*)d_in[11];
    float* out = (float*)d_out;

    __half *xnh, *qkvh, *atth, *xn2h, *hidh;
    __half *wqkv, *wo, *wgh, *wout;
    float *x1;
    cudaGetSymbolAddress((void**)&xnh,   g_xnh);
    cudaGetSymbolAddress((void**)&qkvh,  g_qkvh);
    cudaGetSymbolAddress((void**)&atth,  g_atth);
    cudaGetSymbolAddress((void**)&x1,    g_x1);
    cudaGetSymbolAddress((void**)&xn2h,  g_xn2h);
    cudaGetSymbolAddress((void**)&hidh,  g_hidh);
    cudaGetSymbolAddress((void**)&wqkv,  g_wqkv);
    cudaGetSymbolAddress((void**)&wo,    g_wo);
    cudaGetSymbolAddress((void**)&wgh,   g_wgh);
    cudaGetSymbolAddress((void**)&wout,  g_wout);

    static int smem_set = 0;
    if (!smem_set) {
        cudaFuncSetAttribute(flash_h_kernel,
            cudaFuncAttributeMaxDynamicSharedMemorySize, FA_SMEM);
        cudaFuncSetAttribute(gemm_f16<0, 1, 1>,
            cudaFuncAttributeMaxDynamicSharedMemorySize, HSMEM);
        cudaFuncSetAttribute(gemm256_f16<1, 0>,
            cudaFuncAttributeMaxDynamicSharedMemorySize, HSMEM2);
        cudaFuncSetAttribute(gemm256_f16<0, 1>,
            cudaFuncAttributeMaxDynamicSharedMemorySize, HSMEM2);
        smem_set = 1;
    }

    // fused fp32->fp16 weight converts, single launch (gate|hid interleaved)
    cvt_all_kernel<<<8192, 256>>>(W_q, W_k, W_v, W_o, W_gate, W_hidden, W_out,
                                  wqkv, wo, wgh, wout);

    // 1. attn pre-norm (fp16)
    rmsnorm_h_kernel<<<NT / 2, 256>>>(x, attn_norm_w, xnh);
    // 2. fused QKV projection -> fp16 packed [NT][3072], Q pre-scaled (256-wide tile)
    gemm256_f16<1, 0><<<dim3(QSTR / G2BN, NT / HBM), 256, HSMEM2>>>(
        xnh, wqkv, qkvh, NT, QSTR, DM);
    // 3. attention (fp16 in/out)
    flash_h_kernel<<<dim3(LSEQ / FBQ, NBATCH * NH), 256, FA_SMEM>>>(qkvh, atth);
    // 4. output projection + bias + residual (fp32 out, 128-wide tile)
    gemm_f16<0, 1, 1><<<dim3(DM / HBN, NT / HBM), 256, HSMEM>>>(
        atth, wo, x1, NT, DM, DM, b_o, x);
    // 5. ffn pre-norm (fp16)
    rmsnorm_h_kernel<<<NT / 2, 256>>>(x1, ffn_norm_w, xn2h);
    // 6+7. fused gate+hidden GEMM, swiglu epilogue (256-wide tile)
    gemm256_f16<0, 1><<<dim3(DH2 / G2BN, NT / HBM), 256, HSMEM2>>>(
        xn2h, wgh, hidh, NT, DH2, DM);
    // 8. out projection + bias + residual (fp32 out, 128-wide tile)
    gemm_f16<0, 1, 1><<<dim3(DM / HBN, NT / HBM), 256, HSMEM>>>(
        hidh, wout, out, NT, DM, DH, b_out, x1);
}

// round 17
// speedup vs baseline: 1.0741x; 1.0741x over previous
#include <cuda_runtime.h>
#include <cuda_fp16.h>
#include <math.h>
#include <stdint.h>

#define NT 4096      // total tokens (B*L)
#define DM 1024      // d_model
#define DH 4096      // d_hidden
#define NH 16
#define HD 64
#define LSEQ 2048
#define NBATCH 2
#define QSTR 3072    // packed qkv row stride
#define DH2 (2 * DH) // combined gate|hid interleaved width
#define SCQ 0.18033688f   // 0.125 * log2(e)

// ---------------- scratch (static device globals; no runtime alloc) ----------------
__device__ __half g_xnh [NT * DM];
__device__ __half g_qkvh[(size_t)NT * QSTR];
__device__ __half g_atth[NT * DM];
__device__ float  g_x1  [NT * DM];
__device__ __half g_xn2h[NT * DM];
__device__ __half g_hidh [(size_t)NT * DH];
// fp16 weights, NATURAL [K][N] layout (no transpose)
__device__ __half g_wqkv[(size_t)DM * QSTR];
__device__ __half g_wo  [DM * DM];
__device__ __half g_wgh [(size_t)DM * DH2];   // 8-col-block interleaved gate|hid
__device__ __half g_wout[(size_t)DH * DM];

// ---------------- PTX helpers ----------------
__device__ __forceinline__ void cpa16(uint32_t saddr, const void* src) {
    asm volatile("cp.async.cg.shared.global [%0], [%1], 16;\n" :: "r"(saddr), "l"(src));
}
__device__ __forceinline__ uint32_t s2u(const void* p) {
    uint32_t a;
    asm("{ .reg .u64 t; cvta.to.shared.u64 t, %1; cvt.u32.u64 %0, t; }" : "=r"(a) : "l"(p));
    return a;
}
__device__ __forceinline__ void mma_f16(float* c, const unsigned* a, const unsigned* b) {
    asm volatile("mma.sync.aligned.m16n8k16.row.col.f32.f16.f16.f32 "
        "{%0,%1,%2,%3}, {%4,%5,%6,%7}, {%8,%9}, {%0,%1,%2,%3};\n"
        : "+f"(c[0]), "+f"(c[1]), "+f"(c[2]), "+f"(c[3])
        : "r"(a[0]), "r"(a[1]), "r"(a[2]), "r"(a[3]), "r"(b[0]), "r"(b[1]));
}
__device__ __forceinline__ void ldmx4(unsigned* r, uint32_t addr) {
    asm volatile("ldmatrix.sync.aligned.m8n8.x4.shared.b16 {%0,%1,%2,%3}, [%4];"
        : "=r"(r[0]), "=r"(r[1]), "=r"(r[2]), "=r"(r[3]) : "r"(addr));
}
__device__ __forceinline__ void ldmx4t(unsigned* r, uint32_t addr) {
    asm volatile("ldmatrix.sync.aligned.m8n8.x4.trans.shared.b16 {%0,%1,%2,%3}, [%4];"
        : "=r"(r[0]), "=r"(r[1]), "=r"(r[2]), "=r"(r[3]) : "r"(addr));
}
__device__ __forceinline__ float ex2f(float x) {
    float r; asm("ex2.approx.ftz.f32 %0, %1;" : "=f"(r) : "f"(x)); return r;
}

// ---------------- rmsnorm body (2 rows per block), shared by both launch sites ------
__device__ __forceinline__ void rmsnorm2_body(
    const float* __restrict__ x, const float* __restrict__ w, __half* __restrict__ out,
    int blk)
{
    int half = threadIdx.x >> 7;
    int t = threadIdx.x & 127;
    int row = blk * 2 + half;
    const float4* xr = (const float4*)(x + (size_t)row * DM);
    float4 v0 = xr[t], v1 = xr[t + 128];
    float s = v0.x * v0.x + v0.y * v0.y + v0.z * v0.z + v0.w * v0.w
            + v1.x * v1.x + v1.y * v1.y + v1.z * v1.z + v1.w * v1.w;
    __shared__ float red[2][4];
    #pragma unroll
    for (int o = 16; o > 0; o >>= 1) s += __shfl_xor_sync(0xffffffffu, s, o);
    if ((t & 31) == 0) red[half][t >> 5] = s;
    __syncthreads();
    float tot = red[half][0] + red[half][1] + red[half][2] + red[half][3];
    float inv = rsqrtf(tot * (1.0f / DM) + 1e-6f);
    const float4* wp = (const float4*)w;
    float4 w0 = wp[t], w1 = wp[t + 128];
    __half2* orow = (__half2*)(out + (size_t)row * DM);
    orow[2 * t]       = __floats2half2_rn(w0.x * v0.x * inv, w0.y * v0.y * inv);
    orow[2 * t + 1]   = __floats2half2_rn(w0.z * v0.z * inv, w0.w * v0.w * inv);
    orow[2 * (t + 128)]     = __floats2half2_rn(w1.x * v1.x * inv, w1.y * v1.y * inv);
    orow[2 * (t + 128) + 1] = __floats2half2_rn(w1.z * v1.z * inv, w1.w * v1.w * inv);
}

// ---------------- fused weight convert + attn pre-norm (one launch) ----------------
// blocks [0,8192): fp32->fp16 weight converts (gate/hid 8-col interleaved)
// blocks [8192, 8192+NT/2): rmsnorm of x -> xnh (independent of converts)
__global__ __launch_bounds__(256) void cvt_norm_kernel(
    const float* __restrict__ Wq, const float* __restrict__ Wk, const float* __restrict__ Wv,
    const float* __restrict__ Wo, const float* __restrict__ Wg, const float* __restrict__ Wh,
    const float* __restrict__ Wout2,
    __half* __restrict__ wqkv, __half* __restrict__ wo, __half* __restrict__ wgh,
    __half* __restrict__ wout,
    const float* __restrict__ x, const float* __restrict__ anw, __half* __restrict__ xnh)
{
    int bx = blockIdx.x;
    if (bx >= 8192) {
        rmsnorm2_body(x, anw, xnh, bx - 8192);
        return;
    }
    const float* in; __half* out; int C, outStride, blk, interleave = 0;
    if (bx < 512)        { in = Wq;   out = wqkv;          C = DM; outStride = QSTR; blk = bx; }
    else if (bx < 1024)  { in = Wk;   out = wqkv + DM;     C = DM; outStride = QSTR; blk = bx - 512; }
    else if (bx < 1536)  { in = Wv;   out = wqkv + 2 * DM; C = DM; outStride = QSTR; blk = bx - 1024; }
    else if (bx < 2048)  { in = Wo;   out = wo;            C = DM; outStride = DM;   blk = bx - 1536; }
    else if (bx < 4096)  { in = Wg;   out = wgh;           C = DH; outStride = DH2;  blk = bx - 2048; interleave = 1; }
    else if (bx < 6144)  { in = Wh;   out = wgh + 8;       C = DH; outStride = DH2;  blk = bx - 4096; interleave = 1; }
    else                 { in = Wout2; out = wout;         C = DM; outStride = DM;   blk = bx - 6144; }

    int idx = blk * 256 + threadIdx.x;
    int tpr = C >> 3;
    int row = idx / tpr;
    int col = (idx - row * tpr) * 8;
    const float4* p = (const float4*)(in + (size_t)row * C + col);
    float4 a = p[0], b = p[1];
    __half2 h0 = __floats2half2_rn(a.x, a.y);
    __half2 h1 = __floats2half2_rn(a.z, a.w);
    __half2 h2 = __floats2half2_rn(b.x, b.y);
    __half2 h3 = __floats2half2_rn(b.z, b.w);
    uint4 v;
    v.x = *(unsigned*)&h0; v.y = *(unsigned*)&h1;
    v.z = *(unsigned*)&h2; v.w = *(unsigned*)&h3;
    int ocol = interleave ? 2 * col : col;
    *(uint4*)(out + (size_t)row * outStride + ocol) = v;
}

// ---------------- standalone RMSNorm (FFN pre-norm) ----------------
__global__ __launch_bounds__(256) void rmsnorm_h_kernel(
    const float* __restrict__ x, const float* __restrict__ w, __half* __restrict__ out)
{
    rmsnorm2_body(x, w, out, blockIdx.x);
}

// ================= fp16 tensor-core GEMM, BK=64, 3-stage pipeline (proven) ==========
#define HBM 128
#define HBN 128
#define HBK 64
#define ASTRH 72
#define BSTRH 136
#define ATILE_B (HBM * ASTRH * 2)
#define BTILE_B (HBK * BSTRH * 2)
#define HSTAGE (ATILE_B + BTILE_B)
#define NSTAGE 3
#define HSMEM  (NSTAGE * HSTAGE)

__device__ __forceinline__ void hload(uint32_t s0, const __half* A, const __half* B,
    int bm, int bn, int K, int N, int kk, int tid)
{
    const __half* Ag = A + (size_t)bm * K + kk;
    const __half* Bg = B + (size_t)kk * N + bn;
    #pragma unroll
    for (int j = 0; j < 4; j++) {
        int idx = tid + 256 * j;
        int ar = idx >> 3, ac = idx & 7;
        cpa16(s0 + (uint32_t)(ar * ASTRH + ac * 8) * 2, Ag + (size_t)ar * K + ac * 8);
        int br = idx >> 4, bc = idx & 15;
        cpa16(s0 + (uint32_t)ATILE_B + (uint32_t)(br * BSTRH + bc * 8) * 2,
              Bg + (size_t)br * N + bc * 8);
    }
    asm volatile("cp.async.commit_group;\n" ::: "memory");
}

template <int OUT_HALF, int HAS_BIAS, int HAS_RES, int SWIPAIR, int QSCALE>
__global__ __launch_bounds__(256, 2) void gemm_f16(
    const __half* __restrict__ A, const __half* __restrict__ B, void* __restrict__ Cv,
    int M, int N, int K, const float* __restrict__ bias, const float* __restrict__ res)
{
    extern __shared__ char hsm[];
    uint32_t sbase = s2u(hsm);
    int tid = threadIdx.x;
    int lane = tid & 31, g = lane >> 2, tg = lane & 3;
    int wid = tid >> 5;
    int m_base = (wid >> 1) * 32;
    int n_base = (wid & 1) * 64;
    int bm = blockIdx.y * HBM, bn = blockIdx.x * HBN;
    int lr = lane & 15, lc = lane >> 4;

    float c[2][8][4];
    #pragma unroll
    for (int mt = 0; mt < 2; mt++)
        #pragma unroll
        for (int nt = 0; nt < 8; nt++)
            #pragma unroll
            for (int i = 0; i < 4; i++) c[mt][nt][i] = 0.f;

    const int iters = K / HBK;
    hload(sbase, A, B, bm, bn, K, N, 0, tid);
    hload(sbase + HSTAGE, A, B, bm, bn, K, N, HBK, tid);

    int stage = 0;
    for (int it = 0; it < iters; ++it) {
        if (it + 2 < iters) {
            int ls = stage + 2; if (ls >= NSTAGE) ls -= NSTAGE;
            hload(sbase + (uint32_t)ls * HSTAGE, A, B, bm, bn, K, N, (it + 2) * HBK, tid);
        } else {
            asm volatile("cp.async.commit_group;\n" ::: "memory");
        }
        asm volatile("cp.async.wait_group 2;\n" ::: "memory");
        __syncthreads();

        uint32_t As = sbase + (uint32_t)stage * HSTAGE;
        uint32_t Bs = As + ATILE_B;

        #pragma unroll
        for (int ks = 0; ks < 4; ++ks) {
            unsigned af[2][4];
            #pragma unroll
            for (int mt = 0; mt < 2; ++mt)
                ldmx4(af[mt], As + (uint32_t)((m_base + mt * 16 + lr) * ASTRH
                                              + ks * 16 + lc * 8) * 2);
            #pragma unroll
            for (int ntp = 0; ntp < 4; ++ntp) {
                unsigned bb[4];
                ldmx4t(bb, Bs + (uint32_t)((ks * 16 + lr) * BSTRH
                                           + n_base + ntp * 16 + lc * 8) * 2);
                #pragma unroll
                for (int mt = 0; mt < 2; ++mt) {
                    mma_f16(c[mt][2 * ntp],     af[mt], bb);
                    mma_f16(c[mt][2 * ntp + 1], af[mt], bb + 2);
                }
            }
        }
        __syncthreads();
        if (++stage >= NSTAGE) stage = 0;
    }

    if (SWIPAIR) {
        __half* Ch = (__half*)Cv;
        int NO = N >> 1;
        #pragma unroll
        for (int mt = 0; mt < 2; ++mt) {
            #pragma unroll
            for (int p = 0; p < 4; ++p) {
                int row = bm + m_base + mt * 16 + g;
                int col = ((bn + n_base + p * 16) >> 4) * 8 + 2 * tg;
                size_t o0 = (size_t)row * NO + col;
                size_t o1 = (size_t)(row + 8) * NO + col;
                float g00 = c[mt][2 * p][0], g01 = c[mt][2 * p][1];
                float g10 = c[mt][2 * p][2], g11 = c[mt][2 * p][3];
                float h00 = c[mt][2 * p + 1][0], h01 = c[mt][2 * p + 1][1];
                float h10 = c[mt][2 * p + 1][2], h11 = c[mt][2 * p + 1][3];
                float v00 = h00 * g00 / (1.f + __expf(-g00));
                float v01 = h01 * g01 / (1.f + __expf(-g01));
                float v10 = h10 * g10 / (1.f + __expf(-g10));
                float v11 = h11 * g11 / (1.f + __expf(-g11));
                *(__half2*)(Ch + o0) = __floats2half2_rn(v00, v01);
                *(__half2*)(Ch + o1) = __floats2half2_rn(v10, v11);
            }
        }
        return;
    }

    #pragma unroll
    for (int mt = 0; mt < 2; ++mt) {
        #pragma unroll
        for (int nt = 0; nt < 8; ++nt) {
            int row = bm + m_base + mt * 16 + g;
            int col = bn + n_base + nt * 8 + 2 * tg;
            size_t o0 = (size_t)row * N + col;
            size_t o1 = (size_t)(row + 8) * N + col;
            float v00 = c[mt][nt][0], v01 = c[mt][nt][1];
            float v10 = c[mt][nt][2], v11 = c[mt][nt][3];
            if (HAS_BIAS) {
                float b0v = bias[col], b1v = bias[col + 1];
                v00 += b0v; v01 += b1v; v10 += b0v; v11 += b1v;
            }
            if (HAS_RES) {
                float2 r0 = *(const float2*)(res + o0);
                float2 r1 = *(const float2*)(res + o1);
                v00 += r0.x; v01 += r0.y; v10 += r1.x; v11 += r1.y;
            }
            if (QSCALE) {
                if (col < DM) { v00 *= SCQ; v01 *= SCQ; v10 *= SCQ; v11 *= SCQ; }
            }
            if (OUT_HALF) {
                __half* Ch = (__half*)Cv;
                *(__half2*)(Ch + o0) = __floats2half2_rn(v00, v01);
                *(__half2*)(Ch + o1) = __floats2half2_rn(v10, v11);
            } else {
                float* Cf = (float*)Cv;
                *(float2*)(Cf + o0) = make_float2(v00, v01);
                *(float2*)(Cf + o1) = make_float2(v10, v11);
            }
        }
    }
}

// ================= fp16 flash attention (round-15 proven, Q pre-scaled) ==============
#define FBQ 128
#define FBKV 64
#define FSTRH 72
#define FKV_BYTES (FBKV * FSTRH * 2)
#define FA_SMEM (4 * FKV_BYTES)

__global__ __launch_bounds__(256, 2) void flash_h_kernel(
    const __half* __restrict__ QKV, __half* __restrict__ O)
{
    extern __shared__ __half hsm2[];
    __half* sK = hsm2;
    __half* sV = sK + 2 * FBKV * FSTRH;

    int tid = threadIdx.x;
    int lane = tid & 31, g = lane >> 2, tg = lane & 3;
    int wid = tid >> 5;
    int mrow = wid * 16;

    int bh = blockIdx.y;
    int b = bh >> 4, h = bh & 15;
    int q0 = blockIdx.x * FBQ;
    size_t base = ((size_t)b * LSEQ) * QSTR + (size_t)h * HD;
    const __half* Qp = QKV;
    const __half* Kp = QKV + DM;
    const __half* Vp = QKV + 2 * DM;

    uint32_t sKu = s2u(sK), sVu = s2u(sV);
    int lr = lane & 15, lc = lane >> 4;

    #pragma unroll
    for (int i = 0; i < 4; i++) {
        int flat = tid + 256 * i;
        int r = flat >> 3, c = flat & 7;
        *(uint4*)&sK[r * FSTRH + c * 8] =
            *(const uint4*)(Qp + base + (size_t)(q0 + r) * QSTR + c * 8);
    }
    __syncthreads();
    unsigned aq[4][4];
    #pragma unroll
    for (int ks = 0; ks < 4; ks++)
        ldmx4(aq[ks], sKu + (uint32_t)((mrow + lr) * FSTRH + ks * 16 + lc * 8) * 2);
    __syncthreads();

    #pragma unroll
    for (int j = 0; j < 2; j++) {
        int cid = tid + 256 * j;
        int r = cid >> 3, c = cid & 7;
        cpa16(sKu + (uint32_t)(r * FSTRH + c * 8) * 2,
              Kp + base + (size_t)r * QSTR + c * 8);
        cpa16(sVu + (uint32_t)(r * FSTRH + c * 8) * 2,
              Vp + base + (size_t)r * QSTR + c * 8);
    }
    asm volatile("cp.async.commit_group;\n" ::: "memory");

    float m0 = -1e30f, m1 = -1e30f, l0 = 0.f, l1 = 0.f;
    float co[8][4];
    #pragma unroll
    for (int nt = 0; nt < 8; nt++)
        #pragma unroll
        for (int i = 0; i < 4; i++) co[nt][i] = 0.f;

    int kt = lane >> 3;
    int krow = lane & 7;
    int kn_off = ((kt >> 1) & 1) * 8 + krow;
    int kk_off = (kt & 1) * 8;
    int vrow = lane & 15;
    int vcol = (lane >> 4) << 3;

    const int ITERS = LSEQ / FBKV;
    for (int it = 0; it < ITERS; ++it) {
        if (it + 1 < ITERS) {
            uint32_t stoff = (uint32_t)((it + 1) & 1) * FKV_BYTES;
            size_t kvoff = (size_t)(it + 1) * FBKV * QSTR;
            #pragma unroll
            for (int j = 0; j < 2; j++) {
                int cid = tid + 256 * j;
                int r = cid >> 3, c = cid & 7;
                cpa16(sKu + stoff + (uint32_t)(r * FSTRH + c * 8) * 2,
                      Kp + base + kvoff + (size_t)r * QSTR + c * 8);
                cpa16(sVu + stoff + (uint32_t)(r * FSTRH + c * 8) * 2,
                      Vp + base + kvoff + (size_t)r * QSTR + c * 8);
            }
            asm volatile("cp.async.commit_group;\n" ::: "memory");
            asm volatile("cp.async.wait_group 1;\n" ::: "memory");
        } else {
            asm volatile("cp.async.wait_group 0;\n" ::: "memory");
        }
        __syncthreads();

        int st = it & 1;
        uint32_t kstage = sKu + (uint32_t)st * FKV_BYTES;
        uint32_t vstage = sVu + (uint32_t)st * FKV_BYTES;

        float cs[8][4];
        #pragma unroll
        for (int nt = 0; nt < 8; nt++)
            #pragma unroll
            for (int i = 0; i < 4; i++) cs[nt][i] = 0.f;

        #pragma unroll
        for (int ks = 0; ks < 4; ks++) {
            #pragma unroll
            for (int ntp = 0; ntp < 4; ntp++) {
                unsigned bb[4];
                ldmx4(bb, kstage + (uint32_t)((ntp * 16 + kn_off) * FSTRH
                                              + ks * 16 + kk_off) * 2);
                mma_f16(cs[2 * ntp],     aq[ks], bb);
                mma_f16(cs[2 * ntp + 1], aq[ks], bb + 2);
            }
        }

        float rm0 = -1e30f, rm1 = -1e30f;
        #pragma unroll
        for (int nt = 0; nt < 8; nt++) {
            rm0 = fmaxf(rm0, fmaxf(cs[nt][0], cs[nt][1]));
            rm1 = fmaxf(rm1, fmaxf(cs[nt][2], cs[nt][3]));
        }
        rm0 = fmaxf(rm0, __shfl_xor_sync(0xffffffffu, rm0, 1));
        rm0 = fmaxf(rm0, __shfl_xor_sync(0xffffffffu, rm0, 2));
        rm1 = fmaxf(rm1, __shfl_xor_sync(0xffffffffu, rm1, 1));
        rm1 = fmaxf(rm1, __shfl_xor_sync(0xffffffffu, rm1, 2));
        float mn0 = fmaxf(m0, rm0);
        float mn1 = fmaxf(m1, rm1);

        float ps0 = 0.f, ps1 = 0.f;
        #pragma unroll
        for (int nt = 0; nt < 8; nt++) {
            cs[nt][0] = ex2f(cs[nt][0] - mn0);
            cs[nt][1] = ex2f(cs[nt][1] - mn0);
            cs[nt][2] = ex2f(cs[nt][2] - mn1);
            cs[nt][3] = ex2f(cs[nt][3] - mn1);
            ps0 += cs[nt][0] + cs[nt][1];
            ps1 += cs[nt][2] + cs[nt][3];
        }
        ps0 += __shfl_xor_sync(0xffffffffu, ps0, 1);
        ps0 += __shfl_xor_sync(0xffffffffu, ps0, 2);
        ps1 += __shfl_xor_sync(0xffffffffu, ps1, 1);
        ps1 += __shfl_xor_sync(0xffffffffu, ps1, 2);

        float f0 = ex2f(m0 - mn0);
        float f1 = ex2f(m1 - mn1);
        l0 = l0 * f0 + ps0;
        l1 = l1 * f1 + ps1;
        m0 = mn0; m1 = mn1;
        #pragma unroll
        for (int nt = 0; nt < 8; nt++) {
            co[nt][0] *= f0; co[nt][1] *= f0;
            co[nt][2] *= f1; co[nt][3] *= f1;
        }

        #pragma unroll
        for (int ks = 0; ks < 4; ks++) {
            unsigned ap[4];
            { __half2 hh = __floats2half2_rn(cs[2 * ks][0], cs[2 * ks][1]); ap[0] = *(unsigned*)&hh; }
            { __half2 hh = __floats2half2_rn(cs[2 * ks][2], cs[2 * ks][3]); ap[1] = *(unsigned*)&hh; }
            { __half2 hh = __floats2half2_rn(cs[2 * ks + 1][0], cs[2 * ks + 1][1]); ap[2] = *(unsigned*)&hh; }
            { __half2 hh = __floats2half2_rn(cs[2 * ks + 1][2], cs[2 * ks + 1][3]); ap[3] = *(unsigned*)&hh; }
            #pragma unroll
            for (int ntp = 0; ntp < 4; ntp++) {
                unsigned bb[4];
                ldmx4t(bb, vstage + (uint32_t)((ks * 16 + vrow) * FSTRH
                                               + ntp * 16 + vcol) * 2);
                mma_f16(co[2 * ntp],     ap, bb);
                mma_f16(co[2 * ntp + 1], ap, bb + 2);
            }
        }
        __syncthreads();
    }

    float i0 = 1.f / l0, i1 = 1.f / l1;
    size_t obase = ((size_t)b * LSEQ) * DM + (size_t)h * HD;
    #pragma unroll
    for (int nt = 0; nt < 8; nt++) {
        int col = nt * 8 + 2 * tg;
        size_t o0 = obase + (size_t)(q0 + mrow + g) * DM + col;
        size_t o1 = obase + (size_t)(q0 + mrow + g + 8) * DM + col;
        *(__half2*)(O + o0) = __floats2half2_rn(co[nt][0] * i0, co[nt][1] * i0);
        *(__half2*)(O + o1) = __floats2half2_rn(co[nt][2] * i1, co[nt][3] * i1);
    }
}

// ---------------- launch ----------------
extern "C" void kernel_launch(void* const* d_in, const int* in_sizes, int n_in,
                              void* d_out, int out_size)
{
    const float* x           = (const float*)d_in[0];
    const float* W_q         = (const float*)d_in[1];
    const float* W_k         = (const float*)d_in[2];
    const float* W_v         = (const float*)d_in[3];
    const float* W_o         = (const float*)d_in[4];
    const float* b_o         = (const float*)d_in[5];
    const float* attn_norm_w = (const float*)d_in[6];
    const float* ffn_norm_w  = (const float*)d_in[7];
    const float* W_gate      = (const float*)d_in[8];
    const float* W_hidden    = (const float*)d_in[9];
    const float* W_out       = (const float*)d_in[10];
    const float* b_out       = (const float*)d_in[11];
    float* out = (float*)d_out;

    __half *xnh, *qkvh, *atth, *xn2h, *hidh;
    __half *wqkv, *wo, *wgh, *wout;
    float *x1;
    cudaGetSymbolAddress((void**)&xnh,   g_xnh);
    cudaGetSymbolAddress((void**)&qkvh,  g_qkvh);
    cudaGetSymbolAddress((void**)&atth,  g_atth);
    cudaGetSymbolAddress((void**)&x1,    g_x1);
    cudaGetSymbolAddress((void**)&xn2h,  g_xn2h);
    cudaGetSymbolAddress((void**)&hidh,  g_hidh);
    cudaGetSymbolAddress((void**)&wqkv,  g_wqkv);
    cudaGetSymbolAddress((void**)&wo,    g_wo);
    cudaGetSymbolAddress((void**)&wgh,   g_wgh);
    cudaGetSymbolAddress((void**)&wout,  g_wout);

    static int smem_set = 0;
    if (!smem_set) {
        cudaFuncSetAttribute(flash_h_kernel,
            cudaFuncAttributeMaxDynamicSharedMemorySize, FA_SMEM);
        cudaFuncSetAttribute(gemm_f16<1, 0, 0, 0, 1>,
            cudaFuncAttributeMaxDynamicSharedMemorySize, HSMEM);
        cudaFuncSetAttribute(gemm_f16<0, 1, 1, 0, 0>,
            cudaFuncAttributeMaxDynamicSharedMemorySize, HSMEM);
        cudaFuncSetAttribute(gemm_f16<1, 0, 0, 1, 0>,
            cudaFuncAttributeMaxDynamicSharedMemorySize, HSMEM);
        smem_set = 1;
    }

    // fused: weight converts + attn pre-norm, one launch
    cvt_norm_kernel<<<8192 + NT / 2, 256>>>(
        W_q, W_k, W_v, W_o, W_gate, W_hidden, W_out,
        wqkv, wo, wgh, wout, x, attn_norm_w, xnh);

    // 2. fused QKV projection -> fp16 packed [NT][3072], Q pre-scaled
    gemm_f16<1, 0, 0, 0, 1><<<dim3(QSTR / HBN, NT / HBM), 256, HSMEM>>>(
        xnh, wqkv, qkvh, NT, QSTR, DM, nullptr, nullptr);
    // 3. attention (fp16 in/out)
    flash_h_kernel<<<dim3(LSEQ / FBQ, NBATCH * NH), 256, FA_SMEM>>>(qkvh, atth);
    // 4. output projection + bias + residual (fp32 out)
    gemm_f16<0, 1, 1, 0, 0><<<dim3(DM / HBN, NT / HBM), 256, HSMEM>>>(
        atth, wo, x1, NT, DM, DM, b_o, x);
    // 5. ffn pre-norm (fp16)
    rmsnorm_h_kernel<<<NT / 2, 256>>>(x1, ffn_norm_w, xn2h);
    // 6+7. fused gate+hidden GEMM over interleaved weights, swiglu in epilogue
    gemm_f16<1, 0, 0, 1, 0><<<dim3(DH2 / HBN, NT / HBM), 256, HSMEM>>>(
        xn2h, wgh, hidh, NT, DH2, DM, nullptr, nullptr);
    // 8. out projection + bias + residual (fp32 out)
    gemm_f16<0, 1, 1, 0, 0><<<dim3(DM / HBN, NT / HBM), 256, HSMEM>>>(
        hidh, wout, out, NT, DM, DH, b_out, x1);
}